// round 17
// baseline (speedup 1.0000x reference)
#include <cuda_runtime.h>

#define BSZ    512
#define NN     128
#define NMAT   2560
#define SS     132           // partial stride (words): 132 ≡ 4 (mod 32)
#define TS     36            // warp subtile row stride: 36 ≡ 4 (mod 32)
#define LOG2E  1.4426950408889634f

__device__ __forceinline__ float frcp(float x) {
    float r;
    asm("rcp.approx.ftz.f32 %0, %1;" : "=f"(r) : "f"(x));
    return r;
}
__device__ __forceinline__ float fex2(float x) {
    float r;
    asm("ex2.approx.ftz.f32 %0, %1;" : "=f"(r) : "f"(x));
    return r;
}

// ---------------- persistent scratch (__device__ globals) -------------------
__device__ float g_Ts[128];          // sorted ReLU thresholds
__device__ float g_A [129 * 128];    // per-interval slope * log2e
__device__ float g_Cc[129 * 128];    // per-interval offset * log2e (incl b2)

// ---------------- kernel 1: fused prep (rank + tables + Ts) -----------------
__global__ void k_prep(const float* __restrict__ w1, const float* __restrict__ b1,
                       const float* __restrict__ w2, const float* __restrict__ b2)
{
    __shared__ float tsh[128], wss[128], bss[128];
    __shared__ int   ps[128];
    extern __shared__ float w2t[];    // [128][129] transposed w2

    const int j = threadIdx.x;        // output column 0..127
    const int k = blockIdx.x;         // interval 0..128

    float w  = w1[j];
    float bb = b1[j];
    float tv = (w != 0.0f) ? (-bb / w) : (bb > 0.0f ? -3.0e38f : 3.0e38f);
    tsh[j] = tv;
    __syncthreads();
    int r = 0;
    #pragma unroll 8
    for (int p = 0; p < 128; ++p) {
        float o = tsh[p];
        r += (o < tv) || (o == tv && p < j);
    }
    wss[r] = w;
    bss[r] = bb;
    ps[r]  = j;
    if (k == 0) g_Ts[r] = tv;

    #pragma unroll 4
    for (int t = 0; t < 128; ++t)
        w2t[j * 129 + t] = w2[t * 128 + j];
    __syncthreads();

    float a = 0.f, c = 0.f;
    #pragma unroll 4
    for (int p = 0; p < 128; ++p) {
        float wv = wss[p], bv = bss[p];
        bool pos = (wv > 0.f) || (wv == 0.f && bv > 0.f);
        bool act = pos ? (p < k) : (p >= k);
        if (act) {
            float mm = w2t[ps[p] * 129 + j];
            a = fmaf(wv, mm, a);
            c = fmaf(bv, mm, c);
        }
    }
    g_A [k * 128 + j] = a * LOG2E;
    g_Cc[k * 128 + j] = (c + b2[j]) * LOG2E;
}

// ---------------- kernel 2: column-register Sinkhorn ------------------------
// warp w: g=w>>2 (rows 32g..), q=w&3 (cols 32q..); lane -> row r=32g+lane.
// Thread holds ONLY its column slice cc[8] = M0[32g+j][32q+lane] in regs;
// the row slice is re-read from the warp subtile each iteration (8 CF
// LDS.128). Col dot is pure FFMA + broadcast. 2 CTA barriers/iter,
// warp-redundant R/C reduces into per-warp WR/WC copies.
__global__ __launch_bounds__(512, 2) void k_sinkhorn(
    const float* __restrict__ x,
    const float* __restrict__ noise,
    float* __restrict__ out)
{
    extern __shared__ float sm[];
    float* sub = sm;                      // [16][32*TS] per-warp subtiles
    float* P1  = sm + 16 * 32 * TS;       // [4][SS] row partials (by quarter)
    float* P2  = P1 + 4 * SS;             // [4][SS] col partials (by group)
    float* WR  = P2 + 4 * SS;             // [16][32] per-warp R copies
    float* WC  = WR + 16 * 32;            // [16][32] per-warp C copies

    const int m    = blockIdx.x;
    const int b    = m & (BSZ - 1);
    const int tid  = threadIdx.x;
    const int lane = tid & 31;
    const int wrp  = tid >> 5;
    const int g    = wrp >> 2;
    const int q    = wrp & 3;
    const int r    = 32 * g + lane;

    // ---- own x and interval index (L1/L2-hot __ldg binary search) ----------
    const float xv_own = __ldg(x + b * NN + r);
    int lo = 0, hi = 128;
    #pragma unroll
    for (int s = 0; s < 7; ++s) {
        int mid = (lo + hi) >> 1;
        if (__ldg(g_Ts + mid) < xv_own) lo = mid + 1; else hi = mid;
    }
    const int kr_own = lo;

    // ---- warp-local prologue: 32x32 subtile, 4 rows per step ---------------
    float* mysub = sub + wrp * (32 * TS);
    const float* nz = noise + (size_t)m * (NN * NN) + (32 * g) * NN + 32 * q;
    const int oct = lane >> 3;
    const int c8  = 4 * (lane & 7);
    #pragma unroll
    for (int t = 0; t < 8; ++t) {
        int   src = 4 * t + oct;
        float xr  = __shfl_sync(0xffffffffu, xv_own, src);
        int   kt  = __shfl_sync(0xffffffffu, kr_own, src);
        float4 a4 = *(const float4*)(g_A  + kt * 128 + 32 * q + c8);
        float4 q4 = *(const float4*)(g_Cc + kt * 128 + 32 * q + c8);
        float4 n4 = *(const float4*)(nz + src * NN + c8);
        float4 e;
        e.x = fex2(fmaf(n4.x, LOG2E, fmaf(a4.x, xr, q4.x)));
        e.y = fex2(fmaf(n4.y, LOG2E, fmaf(a4.y, xr, q4.y)));
        e.z = fex2(fmaf(n4.z, LOG2E, fmaf(a4.z, xr, q4.z)));
        e.w = fex2(fmaf(n4.w, LOG2E, fmaf(a4.w, xr, q4.w)));
        *(float4*)(mysub + src * TS + c8) = e;              // CF (stride 36)
    }
    __syncwarp();

    // ---- pickup COLUMN slice into registers (CF scalar LDS, one-time) ------
    float4 cc[8];                          // cc[p].e = M0[32g+4p+e][32q+lane]
    #pragma unroll
    for (int p = 0; p < 8; ++p) {
        cc[p].x = mysub[(4 * p + 0) * TS + lane];
        cc[p].y = mysub[(4 * p + 1) * TS + lane];
        cc[p].z = mysub[(4 * p + 2) * TS + lane];
        cc[p].w = mysub[(4 * p + 3) * TS + lane];
    }

    const float* myrow = mysub + lane * TS;   // row slice (LDS.128 x8, CF)
    const float* myWR  = WR + wrp * 32;
    const float* myWC  = WC + wrp * 32;
    float Rl = 0.f;

    #pragma unroll 1
    for (int it = 0; it < 10; ++it) {
        // ---- (1) row dot: sum(row slice * C)  (it 0: C == 1) ---------------
        float4 acc = make_float4(0.f, 0.f, 0.f, 0.f);
        if (it == 0) {
            #pragma unroll
            for (int p = 0; p < 8; ++p) {
                float4 rv = *(const float4*)(myrow + 4 * p);   // CF LDS.128
                acc.x += rv.x; acc.y += rv.y; acc.z += rv.z; acc.w += rv.w;
            }
        } else {
            #pragma unroll
            for (int p = 0; p < 8; ++p) {
                float4 rv = *(const float4*)(myrow + 4 * p);   // CF LDS.128
                float4 c4 = *(const float4*)(myWC + 4 * p);    // bcast
                acc.x = fmaf(rv.x, c4.x, acc.x);
                acc.y = fmaf(rv.y, c4.y, acc.y);
                acc.z = fmaf(rv.z, c4.z, acc.z);
                acc.w = fmaf(rv.w, c4.w, acc.w);
            }
        }
        P1[q * SS + r] = (acc.x + acc.y) + (acc.z + acc.w);    // CF STS
        __syncthreads();                                       // barrier 1

        // ---- (2) warp-redundant R for own rows -> private WR copy ----------
        Rl = frcp((P1[0 * SS + r] + P1[1 * SS + r]) +
                  (P1[2 * SS + r] + P1[3 * SS + r]));          // CF LDS x4
        WR[wrp * 32 + lane] = Rl;                              // CF STS
        __syncwarp();

        // ---- (3) col dot: sum(cc * R[32g..]) — pure FFMA + broadcast -------
        float4 tac = make_float4(0.f, 0.f, 0.f, 0.f);
        #pragma unroll
        for (int p = 0; p < 8; ++p) {
            float4 rv = *(const float4*)(myWR + 4 * p);        // bcast
            tac.x = fmaf(cc[p].x, rv.x, tac.x);
            tac.y = fmaf(cc[p].y, rv.y, tac.y);
            tac.z = fmaf(cc[p].z, rv.z, tac.z);
            tac.w = fmaf(cc[p].w, rv.w, tac.w);
        }
        P2[g * SS + 32 * q + lane] = (tac.x + tac.y) + (tac.z + tac.w);
        __syncthreads();                                       // barrier 2

        // ---- (4) warp-redundant C for own column -> private WC copy --------
        {
            int ci = 32 * q + lane;
            float cs = frcp((P2[0 * SS + ci] + P2[1 * SS + ci]) +
                            (P2[2 * SS + ci] + P2[3 * SS + ci]));
            WC[wrp * 32 + lane] = cs;
        }
        __syncwarp();
    }

    // ---- epilogue: out[m][c][r] = M0[r][c]*R_r*C_c, direct from row slice --
    {
        float* om = out + (size_t)m * (NN * NN) + (32 * q) * NN + 32 * g + lane;
        #pragma unroll
        for (int p = 0; p < 8; ++p) {
            float4 rv = *(const float4*)(myrow + 4 * p);       // CF LDS.128
            float4 c4 = *(const float4*)(myWC + 4 * p);        // bcast
            om[(4 * p + 0) * NN] = rv.x * Rl * c4.x;   // coalesced STG.32
            om[(4 * p + 1) * NN] = rv.y * Rl * c4.y;
            om[(4 * p + 2) * NN] = rv.z * Rl * c4.z;
            om[(4 * p + 3) * NN] = rv.w * Rl * c4.w;
        }
    }
}

// ---------------- launch ----------------------------------------------------
extern "C" void kernel_launch(void* const* d_in, const int* in_sizes, int n_in,
                              void* d_out, int out_size)
{
    const float* x     = (const float*)d_in[0];
    const float* w1    = (const float*)d_in[1];
    const float* b1    = (const float*)d_in[2];
    const float* w2    = (const float*)d_in[3];
    const float* b2    = (const float*)d_in[4];
    const float* noise = (const float*)d_in[5];
    float* out = (float*)d_out;

    const int prep_smem = 128 * 129 * 4;                    // 66,048 B
    cudaFuncSetAttribute(k_prep, cudaFuncAttributeMaxDynamicSharedMemorySize,
                         prep_smem);
    k_prep<<<129, 128, prep_smem>>>(w1, b1, w2, b2);

    // sub + P1 + P2 + WR + WC
    const int smem_words = 16 * 32 * TS + 2 * 4 * SS + 2 * 16 * 32;
    const int smem_bytes = smem_words * 4;                  // 82,048 B
    cudaFuncSetAttribute(k_sinkhorn, cudaFuncAttributeMaxDynamicSharedMemorySize,
                         smem_bytes);
    k_sinkhorn<<<NMAT, 512, smem_bytes>>>(x, noise, out);
}